// round 9
// baseline (speedup 1.0000x reference)
#include <cuda_runtime.h>
#include <cuda_bf16.h>
#include <math.h>

#define Hn    2048
#define Tn    512
#define INn   128
#define OUTn  128
#define G3n   6144
#define DSTEP 64
#define DINn  4096

#define NBLK  148
#define ETHR  224    // encoder: 7 warps
#define DTHR  512    // decoder: 16 warps
#define FSTR  64     // flag stride: one 256B region per flag (distinct LTS slices)

// ---------------- device scratch ----------------
__device__ float g_enc_gi[Tn * G3n];
__device__ float g_enc_out[Tn * Hn];     // [t][j] for U GEMM
__device__ float g_enc_outT[Hn * Tn];    // [j][t] for ctx dot
__device__ float g_U[Tn * Hn];
__device__ float g_h[2][Hn];
__device__ float g_Wd[Hn];
__device__ float g_scores[Tn];
__device__ float g_din[DINn];
__device__ float g_logits[OUTn];
__device__ int   g_idx;

__device__ __nv_bfloat16 g_decWih_bf[G3n * DINn];
__device__ __nv_bfloat16 g_decWhh_bf[G3n * Hn];
__device__ __nv_bfloat16 g_WW_bf[Hn * Hn];

// padded barrier flags: one 256B region per block per barrier set
__device__ unsigned g_arr_enc[NBLK * FSTR];
__device__ unsigned g_arr_dec[NBLK * FSTR];

// ---------------- memory-order helpers ----------------
__device__ __forceinline__ void st_rel(unsigned* p, unsigned v) {
    asm volatile("st.global.release.gpu.u32 [%0], %1;" :: "l"(p), "r"(v) : "memory");
}
__device__ __forceinline__ unsigned ld_rlx(unsigned* p) {
    unsigned v;
    asm volatile("ld.global.relaxed.gpu.u32 %0, [%1];" : "=r"(v) : "l"(p) : "memory");
    return v;
}

// All-to-all flag barrier with padded flags: post own flag, warp 0 polls all.
// 1 L2 RTT after last arrival; padding keeps per-line poll pressure at ~148.
__device__ __forceinline__ void gbar(unsigned* arr, unsigned gen) {
    __syncthreads();
    if (threadIdx.x == 0) st_rel(&arr[blockIdx.x * FSTR], gen);
    if (threadIdx.x < 32) {
        bool done;
        do {
            done = true;
            for (int i = threadIdx.x; i < NBLK; i += 32)
                done &= (ld_rlx(&arr[i * FSTR]) >= gen);
        } while (!__all_sync(0xffffffffu, done));
        asm volatile("fence.acq_rel.gpu;" ::: "memory");
    }
    __syncthreads();
}

__device__ __forceinline__ float sigmoidf_acc(float x) {
    return 1.0f / (1.0f + expf(-x));
}
__device__ __forceinline__ float blo(unsigned u) { return __int_as_float(u << 16); }
__device__ __forceinline__ float bhi(unsigned u) { return __int_as_float(u & 0xffff0000u); }

#define ACC8(acc, u, hA, hB) \
    acc = fmaf(blo(u.x), hA.x, acc); acc = fmaf(bhi(u.x), hA.y, acc); \
    acc = fmaf(blo(u.y), hA.z, acc); acc = fmaf(bhi(u.y), hA.w, acc); \
    acc = fmaf(blo(u.z), hB.x, acc); acc = fmaf(bhi(u.z), hB.y, acc); \
    acc = fmaf(blo(u.w), hB.z, acc); acc = fmaf(bhi(u.w), hB.w, acc);

// ---------------- init ----------------
__global__ void init_kernel() {
    int i = blockIdx.x * blockDim.x + threadIdx.x;
    if (i < Hn) g_h[0][i] = 0.0f;
    if (i < NBLK * FSTR) { g_arr_enc[i] = 0u; g_arr_dec[i] = 0u; }
    if (i == 0) g_idx = -1;
}

// ---------------- fp32 -> bf16 ----------------
__global__ void f2bf_kernel(const float* __restrict__ in,
                            __nv_bfloat16* __restrict__ out, int n_pairs) {
    int stride = gridDim.x * blockDim.x;
    const float2* in2 = (const float2*)in;
    __nv_bfloat162* out2 = (__nv_bfloat162*)out;
    for (int i = blockIdx.x * blockDim.x + threadIdx.x; i < n_pairs; i += stride)
        out2[i] = __float22bfloat162_rn(in2[i]);
}

// ---------------- tiled GEMM: C[M,N]=A[M,K]@B[N,K]^T + bias; 128x64 tile, 8x4 micro
__global__ void __launch_bounds__(256) gemm_nt_bias(
    const float* __restrict__ A, const float* __restrict__ B,
    const float* __restrict__ bias, float* __restrict__ C,
    int M, int N, int K)
{
    __shared__ float As[16][132];
    __shared__ float Bs[16][68];
    const int m0 = blockIdx.y * 128;
    const int n0 = blockIdx.x * 64;
    const int tid = threadIdx.x;
    const int tx = tid & 15;        // n: 16 groups x 4
    const int ty = tid >> 4;        // m: 16 groups x 8
    float c[8][4] = {};

    for (int k0 = 0; k0 < K; k0 += 16) {
#pragma unroll
        for (int i = 0; i < 8; i++) {
            int idx = tid + i * 256;
            int kk = idx & 15;
            int mm = idx >> 4;
            As[kk][mm] = A[(size_t)(m0 + mm) * K + k0 + kk];
        }
#pragma unroll
        for (int i = 0; i < 4; i++) {
            int idx = tid + i * 256;
            int kk = idx & 15;
            int mm = idx >> 4;
            Bs[kk][mm] = B[(size_t)(n0 + mm) * K + k0 + kk];
        }
        __syncthreads();
#pragma unroll
        for (int kk = 0; kk < 16; kk++) {
            float4 a0 = *(const float4*)&As[kk][ty * 8];
            float4 a1 = *(const float4*)&As[kk][ty * 8 + 4];
            float4 b4 = *(const float4*)&Bs[kk][tx * 4];
            float av[8] = {a0.x, a0.y, a0.z, a0.w, a1.x, a1.y, a1.z, a1.w};
            float bv[4] = {b4.x, b4.y, b4.z, b4.w};
#pragma unroll
            for (int i = 0; i < 8; i++)
#pragma unroll
                for (int j = 0; j < 4; j++)
                    c[i][j] = fmaf(av[i], bv[j], c[i][j]);
        }
        __syncthreads();
    }
#pragma unroll
    for (int i = 0; i < 8; i++) {
        int m = m0 + ty * 8 + i;
#pragma unroll
        for (int j = 0; j < 4; j++) {
            int n = n0 + tx * 4 + j;
            C[(size_t)m * N + n] = c[i][j] + bias[n];
        }
    }
}

// ---------------- persistent encoder: register h, smem bf16 weights -------------
#define ENC_WSMEM (7 * 6 * 1024)
#define ENC_SMEM  (ENC_WSMEM * 4)

__global__ void __launch_bounds__(ETHR, 1) enc_persistent(
    const float* __restrict__ Whh, const float* __restrict__ bhh)
{
    extern __shared__ unsigned sw[];
    const uint4* sw4 = (const uint4*)sw;

    const int warp = threadIdx.x >> 5;
    const int lane = threadIdx.x & 31;
    const int j0 = (blockIdx.x * 7 + warp) * 2;
    const bool active = (j0 < Hn);

    float bR = 0, bZ = 0, bN = 0;
    if (active) {
#pragma unroll
        for (int r = 0; r < 6; r++) {
            const int g = r >> 1, jj = r & 1;
            const float2* src = (const float2*)(Whh + ((size_t)g * Hn + j0 + jj) * Hn);
            unsigned* dst = sw + (warp * 6 + r) * 1024;
            for (int i = lane; i < 1024; i += 32) {
                __nv_bfloat162 b2 = __float22bfloat162_rn(__ldg(src + i));
                dst[i] = *(unsigned*)&b2;
            }
        }
        if (lane < 2) {
            bR = bhh[j0 + lane];
            bZ = bhh[Hn + j0 + lane];
            bN = bhh[2 * Hn + j0 + lane];
        }
    }
    __syncthreads();

    for (int t = 0; t < Tn; t++) {
        if (active) {
            // gi for j0+lane (independent of h; issue first)
            float giR = 0, giZ = 0, giN = 0;
            if (lane < 2) {
                const float* gi = g_enc_gi + (size_t)t * G3n;
                giR = __ldcs(gi + j0 + lane);
                giZ = __ldcs(gi + Hn + j0 + lane);
                giN = __ldcs(gi + 2 * Hn + j0 + lane);
            }
            // h straight into registers (no staging, no block sync)
            const float* hin = g_h[t & 1];
            const float4* hg4 = (const float4*)hin;
            float hp = 0.f;
            if (lane < 2) hp = __ldcg(hin + j0 + lane);
            float4 hreg[16];
#pragma unroll
            for (int c = 0; c < 8; c++) {
                hreg[2 * c]     = __ldcg(hg4 + 2 * (c * 32 + lane));
                hreg[2 * c + 1] = __ldcg(hg4 + 2 * (c * 32 + lane) + 1);
            }

            const uint4* w = sw4 + (size_t)warp * 6 * 256;
            float aR0 = 0, aR1 = 0, aZ0 = 0, aZ1 = 0, aN0 = 0, aN1 = 0;
#pragma unroll
            for (int c = 0; c < 8; c++) {
                const int idx = c * 32 + lane;
                float4 hA = hreg[2 * c];
                float4 hB = hreg[2 * c + 1];
                uint4 uR0 = w[idx];
                uint4 uR1 = w[256 + idx];
                uint4 uZ0 = w[512 + idx];
                uint4 uZ1 = w[768 + idx];
                uint4 uN0 = w[1024 + idx];
                uint4 uN1 = w[1280 + idx];
                ACC8(aR0, uR0, hA, hB)
                ACC8(aR1, uR1, hA, hB)
                ACC8(aZ0, uZ0, hA, hB)
                ACC8(aZ1, uZ1, hA, hB)
                ACC8(aN0, uN0, hA, hB)
                ACC8(aN1, uN1, hA, hB)
            }
#pragma unroll
            for (int off = 16; off > 0; off >>= 1) {
                aR0 += __shfl_xor_sync(0xffffffffu, aR0, off);
                aR1 += __shfl_xor_sync(0xffffffffu, aR1, off);
                aZ0 += __shfl_xor_sync(0xffffffffu, aZ0, off);
                aZ1 += __shfl_xor_sync(0xffffffffu, aZ1, off);
                aN0 += __shfl_xor_sync(0xffffffffu, aN0, off);
                aN1 += __shfl_xor_sync(0xffffffffu, aN1, off);
            }
            if (lane < 2) {
                const int j = j0 + lane;
                float aR = (lane == 0) ? aR0 : aR1;
                float aZ = (lane == 0) ? aZ0 : aZ1;
                float aN = (lane == 0) ? aN0 : aN1;
                float r = sigmoidf_acc(giR + aR + bR);
                float z = sigmoidf_acc(giZ + aZ + bZ);
                float n = tanhf(giN + r * (aN + bN));
                float hv = (1.0f - z) * n + z * hp;
                g_h[(t + 1) & 1][j] = hv;
                g_enc_out[(size_t)t * Hn + j] = hv;
                g_enc_outT[(size_t)j * Tn + t] = hv;
            }
        }
        gbar(g_arr_enc, (unsigned)(t + 1));
    }
}

// ---------------- persistent decoder: Whh in SMEM, 4 barriers/step -------------
#define DEC_WHH_BYTES (14 * 3 * Hn * 2)              // 172032
#define DEC_SMEM (DEC_WHH_BYTES + (DINn + Hn) * 4)   // 196608

__global__ void __launch_bounds__(DTHR, 1) dec_persistent(
    const float* __restrict__ dec_bih, const float* __restrict__ dec_bhh,
    const float* __restrict__ h2o_W, const float* __restrict__ h2o_b,
    const float* __restrict__ W_b,
    const float* __restrict__ attn_W, const float* __restrict__ attn_b,
    const float* __restrict__ o2h_W, const float* __restrict__ o2h_b,
    float* __restrict__ d_out)
{
    extern __shared__ char dsm[];
    __nv_bfloat16* swhh = (__nv_bfloat16*)dsm;
    float* sbuf = (float*)(dsm + DEC_WHH_BYTES);
    __shared__ float s_red[16];
    __shared__ float s_fval[16];
    __shared__ int   s_fidx[16];
    __shared__ float s_mx, s_lse;
    __shared__ int   s_am;

    const int warp = threadIdx.x >> 5;
    const int lane = threadIdx.x & 31;
    const int tid = threadIdx.x;
    const int bid = blockIdx.x;
    unsigned gen = 0;

    // preload this block's dec_Whh rows (once, reused 64 steps)
    if (warp < 14) {
        const int j = bid * 14 + warp;
        if (j < Hn) {
#pragma unroll
            for (int r = 0; r < 3; r++) {
                const uint4* src = (const uint4*)g_decWhh_bf + (size_t)(r * Hn + j) * (Hn / 8);
                uint4* dst = (uint4*)(swhh + ((size_t)warp * 3 + r) * Hn);
                for (int i = lane; i < Hn / 8; i += 32) dst[i] = __ldg(src + i);
            }
        }
    }
    __syncthreads();

    for (int s = 0; s < DSTEP; s++) {
        const float* hin = g_h[s & 1];

        // ---- Phase A: stage h; Wd (warps 0..13); logits of h_s (warps 14..15, bid<64)
        {
            float4* sh4 = (float4*)sbuf;
            const float4* hg4 = (const float4*)hin;
#pragma unroll
            for (int i = tid; i < Hn / 4; i += DTHR) sh4[i] = __ldcg(hg4 + i);
            __syncthreads();
            if (warp < 14) {
                const int j = bid * 14 + warp;
                if (j < Hn) {
                    const uint4* row = (const uint4*)g_WW_bf + (size_t)j * (Hn / 8);
                    float acc = 0.f;
#pragma unroll
                    for (int c = 0; c < 8; c++) {
                        const int idx = c * 32 + lane;
                        float4 hA = sh4[2 * idx];
                        float4 hB = sh4[2 * idx + 1];
                        uint4 u = __ldg(row + idx);
                        ACC8(acc, u, hA, hB)
                    }
#pragma unroll
                    for (int off = 16; off > 0; off >>= 1)
                        acc += __shfl_down_sync(0xffffffffu, acc, off);
                    if (lane == 0) g_Wd[j] = acc + __ldg(W_b + j);
                }
            } else if (bid < 64) {
                const int o = bid * 2 + (warp - 14);   // 0..127
                const float4* row = (const float4*)(h2o_W + (size_t)o * Hn);
                float acc = 0.f;
#pragma unroll 4
                for (int c = 0; c < Hn / 128; c++) {
                    float4 w = __ldg(row + c * 32 + lane);
                    float4 hv = sh4[c * 32 + lane];
                    acc = fmaf(w.x, hv.x, acc); acc = fmaf(w.y, hv.y, acc);
                    acc = fmaf(w.z, hv.z, acc); acc = fmaf(w.w, hv.w, acc);
                }
#pragma unroll
                for (int off = 16; off > 0; off >>= 1)
                    acc += __shfl_down_sync(0xffffffffu, acc, off);
                if (lane == 0) g_logits[o] = acc + __ldg(h2o_b + o);
            }
        }
        gen++; gbar(g_arr_dec, gen);

        // ---- Phase B: scores (bid<128) | argmax + outs row s-1 (bid==128, s>0) ----
        if (bid < 128) {
            float4* swd = (float4*)sbuf;
            const float4* wd4 = (const float4*)g_Wd;
#pragma unroll
            for (int i = tid; i < Hn / 4; i += DTHR) swd[i] = __ldcg(wd4 + i);
            __syncthreads();
            if (warp < 4) {
                const int t = bid * 4 + warp;   // 0..511
                const float4* u4 = (const float4*)(g_U + (size_t)t * Hn);
                const float4* aw4 = (const float4*)attn_W;
                float acc = 0.f;
#pragma unroll 4
                for (int c = 0; c < Hn / 128; c++) {
                    float4 u = __ldg(u4 + c * 32 + lane);
                    float4 d = swd[c * 32 + lane];
                    float4 w = __ldg(aw4 + c * 32 + lane);
                    acc = fmaf(tanhf(u.x + d.x), w.x, acc);
                    acc = fmaf(tanhf(u.y + d.y), w.y, acc);
                    acc = fmaf(tanhf(u.z + d.z), w.z, acc);
                    acc = fmaf(tanhf(u.w + d.w), w.w, acc);
                }
#pragma unroll
                for (int off = 16; off > 0; off >>= 1)
                    acc += __shfl_down_sync(0xffffffffu, acc, off);
                if (lane == 0) g_scores[t] = acc + __ldg(attn_b);
            }
        } else if (bid == 128 && s > 0) {
            float lv = (tid < OUTn) ? __ldcg(g_logits + tid) : -INFINITY;
            float v = lv;
            int vi = tid;
#pragma unroll
            for (int off = 16; off > 0; off >>= 1) {
                float ov = __shfl_xor_sync(0xffffffffu, v, off);
                int oi = __shfl_xor_sync(0xffffffffu, vi, off);
                if (ov > v || (ov == v && oi < vi)) { v = ov; vi = oi; }
            }
            if (lane == 0) { s_fval[warp] = v; s_fidx[warp] = vi; }
            __syncthreads();
            if (tid == 0) {
                float mv = s_fval[0]; int mi = s_fidx[0];
#pragma unroll
                for (int w = 1; w < 16; w++)
                    if (s_fval[w] > mv || (s_fval[w] == mv && s_fidx[w] < mi)) {
                        mv = s_fval[w]; mi = s_fidx[w];
                    }
                s_mx = mv; s_am = mi;
            }
            __syncthreads();
            float mx = s_mx;
            float e = (tid < OUTn) ? expf(lv - mx) : 0.f;
            float sum = e;
#pragma unroll
            for (int off = 16; off > 0; off >>= 1)
                sum += __shfl_xor_sync(0xffffffffu, sum, off);
            if (lane == 0) s_fval[warp] = sum;
            __syncthreads();
            if (tid == 0) {
                float tot = 0.f;
#pragma unroll
                for (int w = 0; w < 16; w++) tot += s_fval[w];
                s_lse = logf(tot);
                g_idx = s_am;
            }
            __syncthreads();
            if (tid < OUTn)
                d_out[(size_t)(s - 1) * OUTn + tid] = lv - mx - s_lse;
        }
        gen++; gbar(g_arr_dec, gen);

        // ---- Phase C: softmax; ctx+din (bid<128, 16 jj each) | attns out (bid==128)
        if (bid <= 128) {
            float v = __ldcg(g_scores + tid);
            float m = v;
#pragma unroll
            for (int off = 16; off > 0; off >>= 1)
                m = fmaxf(m, __shfl_xor_sync(0xffffffffu, m, off));
            if (lane == 0) s_red[warp] = m;
            __syncthreads();
            float mx = s_red[0];
#pragma unroll
            for (int w = 1; w < 16; w++) mx = fmaxf(mx, s_red[w]);
            __syncthreads();
            float e = expf(v - mx);
            float sum = e;
#pragma unroll
            for (int off = 16; off > 0; off >>= 1)
                sum += __shfl_xor_sync(0xffffffffu, sum, off);
            if (lane == 0) s_red[warp] = sum;
            __syncthreads();
            float tot = 0.f;
#pragma unroll
            for (int w = 0; w < 16; w++) tot += s_red[w];
            float aw = e / tot;
            sbuf[tid] = aw;
            __syncthreads();
            if (bid == 128) {
                d_out[DSTEP * OUTn + (size_t)s * Tn + tid] = aw;
            } else {
                const int jj = bid * 16 + warp;   // 0..2047
                const float4* row = (const float4*)(g_enc_outT + (size_t)jj * Tn);
                const float4* aw4 = (const float4*)sbuf;
                float acc = 0.f;
#pragma unroll
                for (int c = 0; c < 4; c++) {
                    const int idx = c * 32 + lane;
                    float4 a = aw4[idx];
                    float4 eo = __ldg(row + idx);
                    acc = fmaf(a.x, eo.x, acc); acc = fmaf(a.y, eo.y, acc);
                    acc = fmaf(a.z, eo.z, acc); acc = fmaf(a.w, eo.w, acc);
                }
#pragma unroll
                for (int off = 16; off > 0; off >>= 1)
                    acc += __shfl_down_sync(0xffffffffu, acc, off);
                if (lane == 0) {
                    g_din[Hn + jj] = acc;
                    int idx;
                    asm volatile("ld.global.cg.s32 %0, [%1];" : "=r"(idx) : "l"(&g_idx));
                    float emb = __ldg(o2h_b + jj);
                    if (idx >= 0) emb += __ldg(o2h_W + (size_t)jj * OUTn + idx);
                    g_din[jj] = emb;
                }
            }
        }
        gen++; gbar(g_arr_dec, gen);

        // ---- Phase E: decoder GRU (warps 0..13; Whh from SMEM) ----
        {
            float* sdin = sbuf;
            float* shh = sbuf + DINn;
            float4* sdin4 = (float4*)sdin;
            float4* shh4 = (float4*)shh;
            const float4* dg4 = (const float4*)g_din;
            const float4* hg4 = (const float4*)hin;
#pragma unroll
            for (int i = tid; i < DINn / 4; i += DTHR) sdin4[i] = __ldcg(dg4 + i);
#pragma unroll
            for (int i = tid; i < Hn / 4; i += DTHR) shh4[i] = __ldcg(hg4 + i);
            __syncthreads();

            const int j = bid * 14 + warp;
            if (warp < 14 && j < Hn) {
                const uint4* ir  = (const uint4*)g_decWih_bf + (size_t)j * (DINn / 8);
                const uint4* iz  = (const uint4*)g_decWih_bf + (size_t)(Hn + j) * (DINn / 8);
                const uint4* in_ = (const uint4*)g_decWih_bf + (size_t)(2 * Hn + j) * (DINn / 8);
                const uint4* hr  = (const uint4*)(swhh + ((size_t)warp * 3 + 0) * Hn);
                const uint4* hz  = (const uint4*)(swhh + ((size_t)warp * 3 + 1) * Hn);
                const uint4* hn  = (const uint4*)(swhh + ((size_t)warp * 3 + 2) * Hn);

                float a_r = 0.f, a_z = 0.f, a_in = 0.f, a_hn = 0.f;
#pragma unroll 4
                for (int c = 0; c < 16; c++) {
                    const int idx = c * 32 + lane;
                    float4 dA = sdin4[2 * idx];
                    float4 dB = sdin4[2 * idx + 1];
                    uint4 u0 = __ldg(ir + idx);
                    uint4 u1 = __ldg(iz + idx);
                    uint4 u2 = __ldg(in_ + idx);
                    ACC8(a_r, u0, dA, dB)
                    ACC8(a_z, u1, dA, dB)
                    ACC8(a_in, u2, dA, dB)
                }
#pragma unroll 4
                for (int c = 0; c < 8; c++) {
                    const int idx = c * 32 + lane;
                    float4 hA = shh4[2 * idx];
                    float4 hB = shh4[2 * idx + 1];
                    uint4 u0 = hr[idx];
                    uint4 u1 = hz[idx];
                    uint4 u2 = hn[idx];
                    ACC8(a_r, u0, hA, hB)
                    ACC8(a_z, u1, hA, hB)
                    ACC8(a_hn, u2, hA, hB)
                }
#pragma unroll
                for (int off = 16; off > 0; off >>= 1) {
                    a_r  += __shfl_down_sync(0xffffffffu, a_r,  off);
                    a_z  += __shfl_down_sync(0xffffffffu, a_z,  off);
                    a_in += __shfl_down_sync(0xffffffffu, a_in, off);
                    a_hn += __shfl_down_sync(0xffffffffu, a_hn, off);
                }
                if (lane == 0) {
                    float r = sigmoidf_acc(a_r + __ldg(dec_bih + j) + __ldg(dec_bhh + j));
                    float z = sigmoidf_acc(a_z + __ldg(dec_bih + Hn + j) + __ldg(dec_bhh + Hn + j));
                    float n = tanhf(a_in + __ldg(dec_bih + 2 * Hn + j)
                                    + r * (a_hn + __ldg(dec_bhh + 2 * Hn + j)));
                    g_h[(s + 1) & 1][j] = (1.0f - z) * n + z * shh[j];
                }
            }
        }
        gen++; gbar(g_arr_dec, gen);
    }

    // ---- tail: logits of h_DSTEP + final log_softmax (row DSTEP-1) ----
    if (bid < 8) {
        const int o = bid * 16 + warp;   // 0..127
        const float4* hg4 = (const float4*)g_h[DSTEP & 1];
        const float4* row = (const float4*)(h2o_W + (size_t)o * Hn);
        float acc = 0.f;
#pragma unroll 4
        for (int c = 0; c < Hn / 128; c++) {
            float4 w = __ldg(row + c * 32 + lane);
            float4 hv = __ldcg(hg4 + c * 32 + lane);
            acc = fmaf(w.x, hv.x, acc); acc = fmaf(w.y, hv.y, acc);
            acc = fmaf(w.z, hv.z, acc); acc = fmaf(w.w, hv.w, acc);
        }
#pragma unroll
        for (int off = 16; off > 0; off >>= 1)
            acc += __shfl_down_sync(0xffffffffu, acc, off);
        if (lane == 0) g_logits[o] = acc + __ldg(h2o_b + o);
    }
    gen++; gbar(g_arr_dec, gen);

    if (bid == 0) {
        float lv = (tid < OUTn) ? __ldcg(g_logits + tid) : -INFINITY;
        float v = lv;
#pragma unroll
        for (int off = 16; off > 0; off >>= 1)
            v = fmaxf(v, __shfl_xor_sync(0xffffffffu, v, off));
        if (lane == 0) s_fval[warp] = v;
        __syncthreads();
        if (tid == 0) {
            float mv = s_fval[0];
#pragma unroll
            for (int w = 1; w < 16; w++) mv = fmaxf(mv, s_fval[w]);
            s_mx = mv;
        }
        __syncthreads();
        float mx = s_mx;
        float e = (tid < OUTn) ? expf(lv - mx) : 0.f;
        float sum = e;
#pragma unroll
        for (int off = 16; off > 0; off >>= 1)
            sum += __shfl_xor_sync(0xffffffffu, sum, off);
        if (lane == 0) s_fval[warp] = sum;
        __syncthreads();
        if (tid == 0) {
            float tot = 0.f;
#pragma unroll
            for (int w = 0; w < 16; w++) tot += s_fval[w];
            s_lse = logf(tot);
        }
        __syncthreads();
        if (tid < OUTn)
            d_out[(size_t)(DSTEP - 1) * OUTn + tid] = lv - mx - s_lse;
    }
}

// ---------------- launch ----------------
extern "C" void kernel_launch(void* const* d_in, const int* in_sizes, int n_in,
                              void* d_out, int out_size)
{
    const float* x        = (const float*)d_in[0];
    const float* enc_Wih  = (const float*)d_in[1];
    const float* enc_Whh  = (const float*)d_in[2];
    const float* enc_bih  = (const float*)d_in[3];
    const float* enc_bhh  = (const float*)d_in[4];
    const float* dec_Wih  = (const float*)d_in[5];
    const float* dec_Whh  = (const float*)d_in[6];
    const float* dec_bih  = (const float*)d_in[7];
    const float* dec_bhh  = (const float*)d_in[8];
    const float* h2o_W    = (const float*)d_in[9];
    const float* h2o_b    = (const float*)d_in[10];
    const float* U_W      = (const float*)d_in[11];
    const float* U_b      = (const float*)d_in[12];
    const float* W_W      = (const float*)d_in[13];
    const float* W_b      = (const float*)d_in[14];
    const float* attn_W   = (const float*)d_in[15];
    const float* attn_b   = (const float*)d_in[16];
    const float* o2h_W    = (const float*)d_in[17];
    const float* o2h_b    = (const float*)d_in[18];
    float* out = (float*)d_out;
    (void)in_sizes; (void)n_in; (void)out_size;

    float *gi_ptr, *enc_out_ptr, *U_ptr;
    __nv_bfloat16 *wih_bf, *whh_bf, *ww_bf;
    cudaGetSymbolAddress((void**)&gi_ptr, g_enc_gi);
    cudaGetSymbolAddress((void**)&enc_out_ptr, g_enc_out);
    cudaGetSymbolAddress((void**)&U_ptr, g_U);
    cudaGetSymbolAddress((void**)&wih_bf, g_decWih_bf);
    cudaGetSymbolAddress((void**)&whh_bf, g_decWhh_bf);
    cudaGetSymbolAddress((void**)&ww_bf, g_WW_bf);

    cudaFuncSetAttribute(enc_persistent,
                         cudaFuncAttributeMaxDynamicSharedMemorySize, ENC_SMEM);
    cudaFuncSetAttribute(dec_persistent,
                         cudaFuncAttributeMaxDynamicSharedMemorySize, DEC_SMEM);

    // launch 0
    init_kernel<<<40, 256>>>();
    // launch 1: gi = x @ enc_Wih^T + bih
    gemm_nt_bias<<<dim3(G3n / 64, Tn / 128), 256>>>(x, enc_Wih, enc_bih, gi_ptr,
                                                    Tn, G3n, INn);
    // launch 2
    f2bf_kernel<<<1024, 256>>>(W_W, ww_bf, Hn * Hn / 2);
    // launch 3: encoder
    enc_persistent<<<NBLK, ETHR, ENC_SMEM>>>(enc_Whh, enc_bhh);
    // decoder prep
    f2bf_kernel<<<2048, 256>>>(dec_Wih, wih_bf, G3n * DINn / 2);
    f2bf_kernel<<<2048, 256>>>(dec_Whh, whh_bf, G3n * Hn / 2);
    gemm_nt_bias<<<dim3(Hn / 64, Tn / 128), 256>>>(enc_out_ptr, U_W, U_b, U_ptr,
                                                   Tn, Hn, Hn);
    // decoder
    dec_persistent<<<NBLK, DTHR, DEC_SMEM>>>(dec_bih, dec_bhh, h2o_W, h2o_b, W_b,
                                             attn_W, attn_b, o2h_W, o2h_b, out);
}

// round 10
// speedup vs baseline: 1.1161x; 1.1161x over previous
#include <cuda_runtime.h>
#include <cuda_bf16.h>
#include <math.h>

#define Hn    2048
#define Tn    512
#define INn   128
#define OUTn  128
#define G3n   6144
#define DSTEP 64
#define DINn  4096

#define NBLK  148
#define ETHR  224    // encoder: 7 warps
#define DTHR  512    // decoder: 16 warps
#define FSTR  32     // flag stride: one 128B line per flag

// ---------------- device scratch ----------------
__device__ float g_enc_gi[Tn * G3n];
__device__ float g_enc_out[Tn * Hn];     // [t][j] for U GEMM
__device__ float g_enc_outT[Hn * Tn];    // [j][t] for ctx dot
__device__ float g_U[Tn * Hn];
__device__ float g_h[2][Hn];
__device__ float g_Wd[Hn];
__device__ float g_scores[Tn];
__device__ float g_din[DINn];
__device__ float g_logits[OUTn];
__device__ int   g_idx;

__device__ __nv_bfloat16 g_decWih_bf[G3n * DINn];
__device__ __nv_bfloat16 g_decWhh_bf[G3n * Hn];
__device__ __nv_bfloat16 g_WW_bf[Hn * Hn];

// padded barrier state: one cache line per flag (centralized protocol — settled)
__device__ unsigned g_arr_enc[NBLK * FSTR];
__device__ unsigned g_rel_enc[FSTR];
__device__ unsigned g_arr_dec[NBLK * FSTR];
__device__ unsigned g_rel_dec[FSTR];

// ---------------- memory-order helpers ----------------
__device__ __forceinline__ void st_rel(unsigned* p, unsigned v) {
    asm volatile("st.global.release.gpu.u32 [%0], %1;" :: "l"(p), "r"(v) : "memory");
}
__device__ __forceinline__ unsigned ld_acq(unsigned* p) {
    unsigned v;
    asm volatile("ld.global.acquire.gpu.u32 %0, [%1];" : "=r"(v) : "l"(p) : "memory");
    return v;
}

// centralized flag barrier, padded flags (R8 — best measured)
__device__ __forceinline__ void gbar(unsigned* arr, unsigned* rel, unsigned gen) {
    __syncthreads();
    if (blockIdx.x == 0) {
        if (threadIdx.x >= 1 && threadIdx.x < NBLK)
            while (ld_acq(&arr[threadIdx.x * FSTR]) < gen) { }
        __syncthreads();
        if (threadIdx.x == 0) st_rel(rel, gen);
    } else {
        if (threadIdx.x == 0) {
            st_rel(&arr[blockIdx.x * FSTR], gen);
            while (ld_acq(rel) < gen) { }
        }
        __syncthreads();
    }
}

__device__ __forceinline__ float sigmoidf_acc(float x) {
    return 1.0f / (1.0f + expf(-x));
}
__device__ __forceinline__ float blo(unsigned u) { return __int_as_float(u << 16); }
__device__ __forceinline__ float bhi(unsigned u) { return __int_as_float(u & 0xffff0000u); }

#define ACC8(acc, u, hA, hB) \
    acc = fmaf(blo(u.x), hA.x, acc); acc = fmaf(bhi(u.x), hA.y, acc); \
    acc = fmaf(blo(u.y), hA.z, acc); acc = fmaf(bhi(u.y), hA.w, acc); \
    acc = fmaf(blo(u.z), hB.x, acc); acc = fmaf(bhi(u.z), hB.y, acc); \
    acc = fmaf(blo(u.w), hB.z, acc); acc = fmaf(bhi(u.w), hB.w, acc);

// ---------------- init ----------------
__global__ void init_kernel() {
    int i = blockIdx.x * blockDim.x + threadIdx.x;
    if (i < Hn) g_h[0][i] = 0.0f;
    if (i < NBLK * FSTR) { g_arr_enc[i] = 0u; g_arr_dec[i] = 0u; }
    if (i < FSTR) { g_rel_enc[i] = 0u; g_rel_dec[i] = 0u; }
    if (i == 0) g_idx = -1;
}

// ---------------- fp32 -> bf16 ----------------
__global__ void f2bf_kernel(const float* __restrict__ in,
                            __nv_bfloat16* __restrict__ out, int n_pairs) {
    int stride = gridDim.x * blockDim.x;
    const float2* in2 = (const float2*)in;
    __nv_bfloat162* out2 = (__nv_bfloat162*)out;
    for (int i = blockIdx.x * blockDim.x + threadIdx.x; i < n_pairs; i += stride)
        out2[i] = __float22bfloat162_rn(in2[i]);
}

// ---------------- tiled GEMM: C[M,N]=A[M,K]@B[N,K]^T + bias; 128x64 tile, 8x4 micro
__global__ void __launch_bounds__(256) gemm_nt_bias(
    const float* __restrict__ A, const float* __restrict__ B,
    const float* __restrict__ bias, float* __restrict__ C,
    int M, int N, int K)
{
    __shared__ float As[16][132];
    __shared__ float Bs[16][68];
    const int m0 = blockIdx.y * 128;
    const int n0 = blockIdx.x * 64;
    const int tid = threadIdx.x;
    const int tx = tid & 15;        // n: 16 groups x 4
    const int ty = tid >> 4;        // m: 16 groups x 8
    float c[8][4] = {};

    for (int k0 = 0; k0 < K; k0 += 16) {
#pragma unroll
        for (int i = 0; i < 8; i++) {
            int idx = tid + i * 256;
            int kk = idx & 15;
            int mm = idx >> 4;
            As[kk][mm] = A[(size_t)(m0 + mm) * K + k0 + kk];
        }
#pragma unroll
        for (int i = 0; i < 4; i++) {
            int idx = tid + i * 256;
            int kk = idx & 15;
            int mm = idx >> 4;
            Bs[kk][mm] = B[(size_t)(n0 + mm) * K + k0 + kk];
        }
        __syncthreads();
#pragma unroll
        for (int kk = 0; kk < 16; kk++) {
            float4 a0 = *(const float4*)&As[kk][ty * 8];
            float4 a1 = *(const float4*)&As[kk][ty * 8 + 4];
            float4 b4 = *(const float4*)&Bs[kk][tx * 4];
            float av[8] = {a0.x, a0.y, a0.z, a0.w, a1.x, a1.y, a1.z, a1.w};
            float bv[4] = {b4.x, b4.y, b4.z, b4.w};
#pragma unroll
            for (int i = 0; i < 8; i++)
#pragma unroll
                for (int j = 0; j < 4; j++)
                    c[i][j] = fmaf(av[i], bv[j], c[i][j]);
        }
        __syncthreads();
    }
#pragma unroll
    for (int i = 0; i < 8; i++) {
        int m = m0 + ty * 8 + i;
#pragma unroll
        for (int j = 0; j < 4; j++) {
            int n = n0 + tx * 4 + j;
            C[(size_t)m * N + n] = c[i][j] + bias[n];
        }
    }
}

// ---------------- persistent encoder: register h, smem bf16 weights -------------
#define ENC_WSMEM (7 * 6 * 1024)
#define ENC_SMEM  (ENC_WSMEM * 4)

__global__ void __launch_bounds__(ETHR, 1) enc_persistent(
    const float* __restrict__ Whh, const float* __restrict__ bhh)
{
    extern __shared__ unsigned sw[];
    const uint4* sw4 = (const uint4*)sw;

    const int warp = threadIdx.x >> 5;
    const int lane = threadIdx.x & 31;
    const int j0 = (blockIdx.x * 7 + warp) * 2;
    const bool active = (j0 < Hn);

    float bR = 0, bZ = 0, bN = 0;
    if (active) {
#pragma unroll
        for (int r = 0; r < 6; r++) {
            const int g = r >> 1, jj = r & 1;
            const float2* src = (const float2*)(Whh + ((size_t)g * Hn + j0 + jj) * Hn);
            unsigned* dst = sw + (warp * 6 + r) * 1024;
            for (int i = lane; i < 1024; i += 32) {
                __nv_bfloat162 b2 = __float22bfloat162_rn(__ldg(src + i));
                dst[i] = *(unsigned*)&b2;
            }
        }
        if (lane < 2) {
            bR = bhh[j0 + lane];
            bZ = bhh[Hn + j0 + lane];
            bN = bhh[2 * Hn + j0 + lane];
        }
    }
    __syncthreads();

    for (int t = 0; t < Tn; t++) {
        if (active) {
            // gi for j0+lane (independent of h; issue first)
            float giR = 0, giZ = 0, giN = 0;
            if (lane < 2) {
                const float* gi = g_enc_gi + (size_t)t * G3n;
                giR = __ldcs(gi + j0 + lane);
                giZ = __ldcs(gi + Hn + j0 + lane);
                giN = __ldcs(gi + 2 * Hn + j0 + lane);
            }
            // h straight into registers (no staging, no block sync)
            const float* hin = g_h[t & 1];
            const float4* hg4 = (const float4*)hin;
            float hp = 0.f;
            if (lane < 2) hp = __ldcg(hin + j0 + lane);
            float4 hreg[16];
#pragma unroll
            for (int c = 0; c < 8; c++) {
                hreg[2 * c]     = __ldcg(hg4 + 2 * (c * 32 + lane));
                hreg[2 * c + 1] = __ldcg(hg4 + 2 * (c * 32 + lane) + 1);
            }

            const uint4* w = sw4 + (size_t)warp * 6 * 256;
            float aR0 = 0, aR1 = 0, aZ0 = 0, aZ1 = 0, aN0 = 0, aN1 = 0;
#pragma unroll
            for (int c = 0; c < 8; c++) {
                const int idx = c * 32 + lane;
                float4 hA = hreg[2 * c];
                float4 hB = hreg[2 * c + 1];
                uint4 uR0 = w[idx];
                uint4 uR1 = w[256 + idx];
                uint4 uZ0 = w[512 + idx];
                uint4 uZ1 = w[768 + idx];
                uint4 uN0 = w[1024 + idx];
                uint4 uN1 = w[1280 + idx];
                ACC8(aR0, uR0, hA, hB)
                ACC8(aR1, uR1, hA, hB)
                ACC8(aZ0, uZ0, hA, hB)
                ACC8(aZ1, uZ1, hA, hB)
                ACC8(aN0, uN0, hA, hB)
                ACC8(aN1, uN1, hA, hB)
            }
#pragma unroll
            for (int off = 16; off > 0; off >>= 1) {
                aR0 += __shfl_xor_sync(0xffffffffu, aR0, off);
                aR1 += __shfl_xor_sync(0xffffffffu, aR1, off);
                aZ0 += __shfl_xor_sync(0xffffffffu, aZ0, off);
                aZ1 += __shfl_xor_sync(0xffffffffu, aZ1, off);
                aN0 += __shfl_xor_sync(0xffffffffu, aN0, off);
                aN1 += __shfl_xor_sync(0xffffffffu, aN1, off);
            }
            if (lane < 2) {
                const int j = j0 + lane;
                float aR = (lane == 0) ? aR0 : aR1;
                float aZ = (lane == 0) ? aZ0 : aZ1;
                float aN = (lane == 0) ? aN0 : aN1;
                float r = sigmoidf_acc(giR + aR + bR);
                float z = sigmoidf_acc(giZ + aZ + bZ);
                float n = tanhf(giN + r * (aN + bN));
                float hv = (1.0f - z) * n + z * hp;
                g_h[(t + 1) & 1][j] = hv;
                g_enc_out[(size_t)t * Hn + j] = hv;
                g_enc_outT[(size_t)j * Tn + t] = hv;
            }
        }
        gbar(g_arr_enc, g_rel_enc, (unsigned)(t + 1));
    }
}

// ---------------- persistent decoder: Whh in SMEM, 4 barriers/step -------------
#define DEC_WHH_BYTES (14 * 3 * Hn * 2)              // 172032
#define DEC_SMEM (DEC_WHH_BYTES + (DINn + Hn) * 4)   // 196608

__global__ void __launch_bounds__(DTHR, 1) dec_persistent(
    const float* __restrict__ dec_bih, const float* __restrict__ dec_bhh,
    const float* __restrict__ h2o_W, const float* __restrict__ h2o_b,
    const float* __restrict__ W_b,
    const float* __restrict__ attn_W, const float* __restrict__ attn_b,
    const float* __restrict__ o2h_W, const float* __restrict__ o2h_b,
    float* __restrict__ d_out)
{
    extern __shared__ char dsm[];
    __nv_bfloat16* swhh = (__nv_bfloat16*)dsm;
    float* sbuf = (float*)(dsm + DEC_WHH_BYTES);
    __shared__ float s_red[16];
    __shared__ float s_fval[16];
    __shared__ int   s_fidx[16];
    __shared__ float s_mx, s_lse;
    __shared__ int   s_am;

    const int warp = threadIdx.x >> 5;
    const int lane = threadIdx.x & 31;
    const int tid = threadIdx.x;
    const int bid = blockIdx.x;
    unsigned gen = 0;

    // preload this block's dec_Whh rows (once, reused 64 steps)
    if (warp < 14) {
        const int j = bid * 14 + warp;
        if (j < Hn) {
#pragma unroll
            for (int r = 0; r < 3; r++) {
                const uint4* src = (const uint4*)g_decWhh_bf + (size_t)(r * Hn + j) * (Hn / 8);
                uint4* dst = (uint4*)(swhh + ((size_t)warp * 3 + r) * Hn);
                for (int i = lane; i < Hn / 8; i += 32) dst[i] = __ldg(src + i);
            }
        }
    }
    __syncthreads();

    for (int s = 0; s < DSTEP; s++) {
        const float* hin = g_h[s & 1];

        // ---- Phase A: stage h; Wd (warps 0..13); logits of h_s (warps 14..15, bid<64)
        {
            float4* sh4 = (float4*)sbuf;
            const float4* hg4 = (const float4*)hin;
#pragma unroll
            for (int i = tid; i < Hn / 4; i += DTHR) sh4[i] = __ldcg(hg4 + i);
            __syncthreads();
            if (warp < 14) {
                const int j = bid * 14 + warp;
                if (j < Hn) {
                    const uint4* row = (const uint4*)g_WW_bf + (size_t)j * (Hn / 8);
                    float acc = 0.f;
#pragma unroll
                    for (int c = 0; c < 8; c++) {
                        const int idx = c * 32 + lane;
                        float4 hA = sh4[2 * idx];
                        float4 hB = sh4[2 * idx + 1];
                        uint4 u = __ldg(row + idx);
                        ACC8(acc, u, hA, hB)
                    }
#pragma unroll
                    for (int off = 16; off > 0; off >>= 1)
                        acc += __shfl_down_sync(0xffffffffu, acc, off);
                    if (lane == 0) g_Wd[j] = acc + __ldg(W_b + j);
                }
            } else if (bid < 64) {
                const int o = bid * 2 + (warp - 14);   // 0..127
                const float4* row = (const float4*)(h2o_W + (size_t)o * Hn);
                float acc = 0.f;
#pragma unroll 4
                for (int c = 0; c < Hn / 128; c++) {
                    float4 w = __ldg(row + c * 32 + lane);
                    float4 hv = sh4[c * 32 + lane];
                    acc = fmaf(w.x, hv.x, acc); acc = fmaf(w.y, hv.y, acc);
                    acc = fmaf(w.z, hv.z, acc); acc = fmaf(w.w, hv.w, acc);
                }
#pragma unroll
                for (int off = 16; off > 0; off >>= 1)
                    acc += __shfl_down_sync(0xffffffffu, acc, off);
                if (lane == 0) g_logits[o] = acc + __ldg(h2o_b + o);
            }
        }
        gen++; gbar(g_arr_dec, g_rel_dec, gen);

        // ---- Phase B: scores (bid<128) | argmax + outs row s-1 (bid==128, s>0) ----
        if (bid < 128) {
            float4* swd = (float4*)sbuf;
            const float4* wd4 = (const float4*)g_Wd;
#pragma unroll
            for (int i = tid; i < Hn / 4; i += DTHR) swd[i] = __ldcg(wd4 + i);
            __syncthreads();
            if (warp < 4) {
                const int t = bid * 4 + warp;   // 0..511
                const float4* u4 = (const float4*)(g_U + (size_t)t * Hn);
                const float4* aw4 = (const float4*)attn_W;
                float acc = 0.f;
#pragma unroll 4
                for (int c = 0; c < Hn / 128; c++) {
                    float4 u = __ldg(u4 + c * 32 + lane);
                    float4 d = swd[c * 32 + lane];
                    float4 w = __ldg(aw4 + c * 32 + lane);
                    acc = fmaf(tanhf(u.x + d.x), w.x, acc);
                    acc = fmaf(tanhf(u.y + d.y), w.y, acc);
                    acc = fmaf(tanhf(u.z + d.z), w.z, acc);
                    acc = fmaf(tanhf(u.w + d.w), w.w, acc);
                }
#pragma unroll
                for (int off = 16; off > 0; off >>= 1)
                    acc += __shfl_down_sync(0xffffffffu, acc, off);
                if (lane == 0) g_scores[t] = acc + __ldg(attn_b);
            }
        } else if (bid == 128 && s > 0) {
            float lv = (tid < OUTn) ? __ldcg(g_logits + tid) : -INFINITY;
            float v = lv;
            int vi = tid;
#pragma unroll
            for (int off = 16; off > 0; off >>= 1) {
                float ov = __shfl_xor_sync(0xffffffffu, v, off);
                int oi = __shfl_xor_sync(0xffffffffu, vi, off);
                if (ov > v || (ov == v && oi < vi)) { v = ov; vi = oi; }
            }
            if (lane == 0) { s_fval[warp] = v; s_fidx[warp] = vi; }
            __syncthreads();
            if (tid == 0) {
                float mv = s_fval[0]; int mi = s_fidx[0];
#pragma unroll
                for (int w = 1; w < 16; w++)
                    if (s_fval[w] > mv || (s_fval[w] == mv && s_fidx[w] < mi)) {
                        mv = s_fval[w]; mi = s_fidx[w];
                    }
                s_mx = mv; s_am = mi;
            }
            __syncthreads();
            float mx = s_mx;
            float e = (tid < OUTn) ? expf(lv - mx) : 0.f;
            float sum = e;
#pragma unroll
            for (int off = 16; off > 0; off >>= 1)
                sum += __shfl_xor_sync(0xffffffffu, sum, off);
            if (lane == 0) s_fval[warp] = sum;
            __syncthreads();
            if (tid == 0) {
                float tot = 0.f;
#pragma unroll
                for (int w = 0; w < 16; w++) tot += s_fval[w];
                s_lse = logf(tot);
                g_idx = s_am;
            }
            __syncthreads();
            if (tid < OUTn)
                d_out[(size_t)(s - 1) * OUTn + tid] = lv - mx - s_lse;
        }
        gen++; gbar(g_arr_dec, g_rel_dec, gen);

        // ---- Phase C: softmax; ctx+din (bid<128, 16 jj each) | attns out (bid==128)
        if (bid <= 128) {
            float v = __ldcg(g_scores + tid);
            float m = v;
#pragma unroll
            for (int off = 16; off > 0; off >>= 1)
                m = fmaxf(m, __shfl_xor_sync(0xffffffffu, m, off));
            if (lane == 0) s_red[warp] = m;
            __syncthreads();
            float mx = s_red[0];
#pragma unroll
            for (int w = 1; w < 16; w++) mx = fmaxf(mx, s_red[w]);
            __syncthreads();
            float e = expf(v - mx);
            float sum = e;
#pragma unroll
            for (int off = 16; off > 0; off >>= 1)
                sum += __shfl_xor_sync(0xffffffffu, sum, off);
            if (lane == 0) s_red[warp] = sum;
            __syncthreads();
            float tot = 0.f;
#pragma unroll
            for (int w = 0; w < 16; w++) tot += s_red[w];
            float aw = e / tot;
            sbuf[tid] = aw;
            __syncthreads();
            if (bid == 128) {
                d_out[DSTEP * OUTn + (size_t)s * Tn + tid] = aw;
            } else {
                const int jj = bid * 16 + warp;   // 0..2047
                const float4* row = (const float4*)(g_enc_outT + (size_t)jj * Tn);
                const float4* aw4 = (const float4*)sbuf;
                float acc = 0.f;
#pragma unroll
                for (int c = 0; c < 4; c++) {
                    const int idx = c * 32 + lane;
                    float4 a = aw4[idx];
                    float4 eo = __ldg(row + idx);
                    acc = fmaf(a.x, eo.x, acc); acc = fmaf(a.y, eo.y, acc);
                    acc = fmaf(a.z, eo.z, acc); acc = fmaf(a.w, eo.w, acc);
                }
#pragma unroll
                for (int off = 16; off > 0; off >>= 1)
                    acc += __shfl_down_sync(0xffffffffu, acc, off);
                if (lane == 0) {
                    g_din[Hn + jj] = acc;
                    int idx;
                    asm volatile("ld.global.cg.s32 %0, [%1];" : "=r"(idx) : "l"(&g_idx));
                    float emb = __ldg(o2h_b + jj);
                    if (idx >= 0) emb += __ldg(o2h_W + (size_t)jj * OUTn + idx);
                    g_din[jj] = emb;
                }
            }
        }
        gen++; gbar(g_arr_dec, g_rel_dec, gen);

        // ---- Phase E: decoder GRU (warps 0..13; Whh from SMEM) ----
        {
            float* sdin = sbuf;
            float* shh = sbuf + DINn;
            float4* sdin4 = (float4*)sdin;
            float4* shh4 = (float4*)shh;
            const float4* dg4 = (const float4*)g_din;
            const float4* hg4 = (const float4*)hin;
#pragma unroll
            for (int i = tid; i < DINn / 4; i += DTHR) sdin4[i] = __ldcg(dg4 + i);
#pragma unroll
            for (int i = tid; i < Hn / 4; i += DTHR) shh4[i] = __ldcg(hg4 + i);
            __syncthreads();

            const int j = bid * 14 + warp;
            if (warp < 14 && j < Hn) {
                const uint4* ir  = (const uint4*)g_decWih_bf + (size_t)j * (DINn / 8);
                const uint4* iz  = (const uint4*)g_decWih_bf + (size_t)(Hn + j) * (DINn / 8);
                const uint4* in_ = (const uint4*)g_decWih_bf + (size_t)(2 * Hn + j) * (DINn / 8);
                const uint4* hr  = (const uint4*)(swhh + ((size_t)warp * 3 + 0) * Hn);
                const uint4* hz  = (const uint4*)(swhh + ((size_t)warp * 3 + 1) * Hn);
                const uint4* hn  = (const uint4*)(swhh + ((size_t)warp * 3 + 2) * Hn);

                float a_r = 0.f, a_z = 0.f, a_in = 0.f, a_hn = 0.f;
#pragma unroll 4
                for (int c = 0; c < 16; c++) {
                    const int idx = c * 32 + lane;
                    float4 dA = sdin4[2 * idx];
                    float4 dB = sdin4[2 * idx + 1];
                    uint4 u0 = __ldg(ir + idx);
                    uint4 u1 = __ldg(iz + idx);
                    uint4 u2 = __ldg(in_ + idx);
                    ACC8(a_r, u0, dA, dB)
                    ACC8(a_z, u1, dA, dB)
                    ACC8(a_in, u2, dA, dB)
                }
#pragma unroll 4
                for (int c = 0; c < 8; c++) {
                    const int idx = c * 32 + lane;
                    float4 hA = shh4[2 * idx];
                    float4 hB = shh4[2 * idx + 1];
                    uint4 u0 = hr[idx];
                    uint4 u1 = hz[idx];
                    uint4 u2 = hn[idx];
                    ACC8(a_r, u0, hA, hB)
                    ACC8(a_z, u1, hA, hB)
                    ACC8(a_hn, u2, hA, hB)
                }
#pragma unroll
                for (int off = 16; off > 0; off >>= 1) {
                    a_r  += __shfl_down_sync(0xffffffffu, a_r,  off);
                    a_z  += __shfl_down_sync(0xffffffffu, a_z,  off);
                    a_in += __shfl_down_sync(0xffffffffu, a_in, off);
                    a_hn += __shfl_down_sync(0xffffffffu, a_hn, off);
                }
                if (lane == 0) {
                    float r = sigmoidf_acc(a_r + __ldg(dec_bih + j) + __ldg(dec_bhh + j));
                    float z = sigmoidf_acc(a_z + __ldg(dec_bih + Hn + j) + __ldg(dec_bhh + Hn + j));
                    float n = tanhf(a_in + __ldg(dec_bih + 2 * Hn + j)
                                    + r * (a_hn + __ldg(dec_bhh + 2 * Hn + j)));
                    g_h[(s + 1) & 1][j] = (1.0f - z) * n + z * shh[j];
                }
            }
        }
        gen++; gbar(g_arr_dec, g_rel_dec, gen);
    }

    // ---- tail: logits of h_DSTEP + final log_softmax (row DSTEP-1) ----
    if (bid < 8) {
        const int o = bid * 16 + warp;   // 0..127
        const float4* hg4 = (const float4*)g_h[DSTEP & 1];
        const float4* row = (const float4*)(h2o_W + (size_t)o * Hn);
        float acc = 0.f;
#pragma unroll 4
        for (int c = 0; c < Hn / 128; c++) {
            float4 w = __ldg(row + c * 32 + lane);
            float4 hv = __ldcg(hg4 + c * 32 + lane);
            acc = fmaf(w.x, hv.x, acc); acc = fmaf(w.y, hv.y, acc);
            acc = fmaf(w.z, hv.z, acc); acc = fmaf(w.w, hv.w, acc);
        }
#pragma unroll
        for (int off = 16; off > 0; off >>= 1)
            acc += __shfl_down_sync(0xffffffffu, acc, off);
        if (lane == 0) g_logits[o] = acc + __ldg(h2o_b + o);
    }
    gen++; gbar(g_arr_dec, g_rel_dec, gen);

    if (bid == 0) {
        float lv = (tid < OUTn) ? __ldcg(g_logits + tid) : -INFINITY;
        float v = lv;
#pragma unroll
        for (int off = 16; off > 0; off >>= 1)
            v = fmaxf(v, __shfl_xor_sync(0xffffffffu, v, off));
        if (lane == 0) s_fval[warp] = v;
        __syncthreads();
        if (tid == 0) {
            float mv = s_fval[0];
#pragma unroll
            for (int w = 1; w < 16; w++) mv = fmaxf(mv, s_fval[w]);
            s_mx = mv;
        }
        __syncthreads();
        float mx = s_mx;
        float e = (tid < OUTn) ? expf(lv - mx) : 0.f;
        float sum = e;
#pragma unroll
        for (int off = 16; off > 0; off >>= 1)
            sum += __shfl_xor_sync(0xffffffffu, sum, off);
        if (lane == 0) s_fval[warp] = sum;
        __syncthreads();
        if (tid == 0) {
            float tot = 0.f;
#pragma unroll
            for (int w = 0; w < 16; w++) tot += s_fval[w];
            s_lse = logf(tot);
        }
        __syncthreads();
        if (tid < OUTn)
            d_out[(size_t)(DSTEP - 1) * OUTn + tid] = lv - mx - s_lse;
    }
}

// ---------------- launch ----------------
extern "C" void kernel_launch(void* const* d_in, const int* in_sizes, int n_in,
                              void* d_out, int out_size)
{
    const float* x        = (const float*)d_in[0];
    const float* enc_Wih  = (const float*)d_in[1];
    const float* enc_Whh  = (const float*)d_in[2];
    const float* enc_bih  = (const float*)d_in[3];
    const float* enc_bhh  = (const float*)d_in[4];
    const float* dec_Wih  = (const float*)d_in[5];
    const float* dec_Whh  = (const float*)d_in[6];
    const float* dec_bih  = (const float*)d_in[7];
    const float* dec_bhh  = (const float*)d_in[8];
    const float* h2o_W    = (const float*)d_in[9];
    const float* h2o_b    = (const float*)d_in[10];
    const float* U_W      = (const float*)d_in[11];
    const float* U_b      = (const float*)d_in[12];
    const float* W_W      = (const float*)d_in[13];
    const float* W_b      = (const float*)d_in[14];
    const float* attn_W   = (const float*)d_in[15];
    const float* attn_b   = (const float*)d_in[16];
    const float* o2h_W    = (const float*)d_in[17];
    const float* o2h_b    = (const float*)d_in[18];
    float* out = (float*)d_out;
    (void)in_sizes; (void)n_in; (void)out_size;

    float *gi_ptr, *enc_out_ptr, *U_ptr;
    __nv_bfloat16 *wih_bf, *whh_bf, *ww_bf;
    cudaGetSymbolAddress((void**)&gi_ptr, g_enc_gi);
    cudaGetSymbolAddress((void**)&enc_out_ptr, g_enc_out);
    cudaGetSymbolAddress((void**)&U_ptr, g_U);
    cudaGetSymbolAddress((void**)&wih_bf, g_decWih_bf);
    cudaGetSymbolAddress((void**)&whh_bf, g_decWhh_bf);
    cudaGetSymbolAddress((void**)&ww_bf, g_WW_bf);

    cudaFuncSetAttribute(enc_persistent,
                         cudaFuncAttributeMaxDynamicSharedMemorySize, ENC_SMEM);
    cudaFuncSetAttribute(dec_persistent,
                         cudaFuncAttributeMaxDynamicSharedMemorySize, DEC_SMEM);

    // launch 0
    init_kernel<<<40, 256>>>();
    // launch 1: gi = x @ enc_Wih^T + bih
    gemm_nt_bias<<<dim3(G3n / 64, Tn / 128), 256>>>(x, enc_Wih, enc_bih, gi_ptr,
                                                    Tn, G3n, INn);
    // launch 2
    f2bf_kernel<<<1024, 256>>>(W_W, ww_bf, Hn * Hn / 2);
    // launch 3: encoder
    enc_persistent<<<NBLK, ETHR, ENC_SMEM>>>(enc_Whh, enc_bhh);
    // decoder prep
    f2bf_kernel<<<2048, 256>>>(dec_Wih, wih_bf, G3n * DINn / 2);
    f2bf_kernel<<<2048, 256>>>(dec_Whh, whh_bf, G3n * Hn / 2);
    gemm_nt_bias<<<dim3(Hn / 64, Tn / 128), 256>>>(enc_out_ptr, U_W, U_b, U_ptr,
                                                   Tn, Hn, Hn);
    // decoder
    dec_persistent<<<NBLK, DTHR, DEC_SMEM>>>(dec_bih, dec_bhh, h2o_W, h2o_b, W_b,
                                             attn_W, attn_b, o2h_W, o2h_b, out);
}

// round 11
// speedup vs baseline: 1.4160x; 1.2688x over previous
#include <cuda_runtime.h>
#include <cuda_bf16.h>
#include <math.h>

#define Hn    2048
#define Tn    512
#define INn   128
#define OUTn  128
#define G3n   6144
#define DSTEP 64
#define DINn  4096

#define NBLK  148
#define ETHR  256    // encoder: 8 warps (7 compute + staging help)
#define DTHR  512    // decoder: 16 warps
#define FSTR  32     // flag stride: one 128B line per flag

// ---------------- device scratch ----------------
__device__ float g_enc_gi[Tn * G3n];
__device__ float g_enc_out[Tn * Hn];     // [t][j] for U GEMM
__device__ float g_enc_outT[Hn * Tn];    // [j][t] for ctx dot
__device__ float g_U[Tn * Hn];
__device__ float g_h[2][Hn];
__device__ float g_Wd[Hn];
__device__ float g_scores[Tn];
__device__ float g_din[DINn];
__device__ float g_logits[OUTn];
__device__ int   g_idx;

__device__ __nv_bfloat16 g_decWih_bf[G3n * DINn];
__device__ __nv_bfloat16 g_decWhh_bf[G3n * Hn];
__device__ __nv_bfloat16 g_WW_bf[Hn * Hn];

// padded barrier state: one cache line per flag (centralized protocol — settled)
__device__ unsigned g_arr_enc[NBLK * FSTR];
__device__ unsigned g_rel_enc[FSTR];
__device__ unsigned g_arr_dec[NBLK * FSTR];
__device__ unsigned g_rel_dec[FSTR];

// ---------------- memory-order helpers ----------------
__device__ __forceinline__ void st_rel(unsigned* p, unsigned v) {
    asm volatile("st.global.release.gpu.u32 [%0], %1;" :: "l"(p), "r"(v) : "memory");
}
__device__ __forceinline__ unsigned ld_acq(unsigned* p) {
    unsigned v;
    asm volatile("ld.global.acquire.gpu.u32 %0, [%1];" : "=r"(v) : "l"(p) : "memory");
    return v;
}

// centralized flag barrier, padded flags (R8 — best measured)
__device__ __forceinline__ void gbar(unsigned* arr, unsigned* rel, unsigned gen) {
    __syncthreads();
    if (blockIdx.x == 0) {
        if (threadIdx.x >= 1 && threadIdx.x < NBLK)
            while (ld_acq(&arr[threadIdx.x * FSTR]) < gen) { }
        __syncthreads();
        if (threadIdx.x == 0) st_rel(rel, gen);
    } else {
        if (threadIdx.x == 0) {
            st_rel(&arr[blockIdx.x * FSTR], gen);
            while (ld_acq(rel) < gen) { }
        }
        __syncthreads();
    }
}

__device__ __forceinline__ float sigmoidf_acc(float x) {
    return 1.0f / (1.0f + expf(-x));
}
__device__ __forceinline__ float blo(unsigned u) { return __int_as_float(u << 16); }
__device__ __forceinline__ float bhi(unsigned u) { return __int_as_float(u & 0xffff0000u); }

#define ACC8(acc, u, hA, hB) \
    acc = fmaf(blo(u.x), hA.x, acc); acc = fmaf(bhi(u.x), hA.y, acc); \
    acc = fmaf(blo(u.y), hA.z, acc); acc = fmaf(bhi(u.y), hA.w, acc); \
    acc = fmaf(blo(u.z), hB.x, acc); acc = fmaf(bhi(u.z), hB.y, acc); \
    acc = fmaf(blo(u.w), hB.z, acc); acc = fmaf(bhi(u.w), hB.w, acc);

// ---------------- init ----------------
__global__ void init_kernel() {
    int i = blockIdx.x * blockDim.x + threadIdx.x;
    if (i < Hn) g_h[0][i] = 0.0f;
    if (i < NBLK * FSTR) { g_arr_enc[i] = 0u; g_arr_dec[i] = 0u; }
    if (i < FSTR) { g_rel_enc[i] = 0u; g_rel_dec[i] = 0u; }
    if (i == 0) g_idx = -1;
}

// ---------------- fp32 -> bf16 ----------------
__global__ void f2bf_kernel(const float* __restrict__ in,
                            __nv_bfloat16* __restrict__ out, int n_pairs) {
    int stride = gridDim.x * blockDim.x;
    const float2* in2 = (const float2*)in;
    __nv_bfloat162* out2 = (__nv_bfloat162*)out;
    for (int i = blockIdx.x * blockDim.x + threadIdx.x; i < n_pairs; i += stride)
        out2[i] = __float22bfloat162_rn(in2[i]);
}

// ---------------- tiled GEMM: C[M,N] = A[M,K] @ B[N,K]^T + bias (R8 version) ----
__global__ void __launch_bounds__(256) gemm_nt_bias(
    const float* __restrict__ A, const float* __restrict__ B,
    const float* __restrict__ bias, float* __restrict__ C,
    int M, int N, int K)
{
    __shared__ float As[16][68];
    __shared__ float Bs[16][68];
    const int m0 = blockIdx.y * 64;
    const int n0 = blockIdx.x * 64;
    const int tid = threadIdx.x;
    const int tx = tid & 15;
    const int ty = tid >> 4;
    float c[4][4] = {};

    for (int k0 = 0; k0 < K; k0 += 16) {
#pragma unroll
        for (int i = 0; i < 4; i++) {
            int idx = tid + i * 256;
            int kk = idx & 15;
            int mm = idx >> 4;
            As[kk][mm] = A[(size_t)(m0 + mm) * K + k0 + kk];
            Bs[kk][mm] = B[(size_t)(n0 + mm) * K + k0 + kk];
        }
        __syncthreads();
#pragma unroll
        for (int kk = 0; kk < 16; kk++) {
            float4 a4 = *(const float4*)&As[kk][ty * 4];
            float4 b4 = *(const float4*)&Bs[kk][tx * 4];
            float av[4] = {a4.x, a4.y, a4.z, a4.w};
            float bv[4] = {b4.x, b4.y, b4.z, b4.w};
#pragma unroll
            for (int i = 0; i < 4; i++)
#pragma unroll
                for (int j = 0; j < 4; j++)
                    c[i][j] = fmaf(av[i], bv[j], c[i][j]);
        }
        __syncthreads();
    }
#pragma unroll
    for (int i = 0; i < 4; i++) {
        int m = m0 + ty * 4 + i;
#pragma unroll
        for (int j = 0; j < 4; j++) {
            int n = n0 + tx * 4 + j;
            C[(size_t)m * N + n] = c[i][j] + bias[n];
        }
    }
}

// ---------------- persistent encoder (R8: smem-staged h) ----------------
#define ENC_WSMEM (7 * 6 * 1024)
#define ENC_SMEM  (ENC_WSMEM * 4 + Hn * 4)

__global__ void __launch_bounds__(ETHR, 1) enc_persistent(
    const float* __restrict__ Whh, const float* __restrict__ bhh)
{
    extern __shared__ char smem_raw[];
    unsigned* sw = (unsigned*)smem_raw;
    float* shh = (float*)(smem_raw + ENC_WSMEM * 4);
    float4* shh4 = (float4*)shh;
    const uint4* sw4 = (const uint4*)sw;

    const int warp = threadIdx.x >> 5;
    const int lane = threadIdx.x & 31;
    const int tid = threadIdx.x;
    const int j0 = (blockIdx.x * 7 + warp) * 2;
    const bool active = (warp < 7) && (j0 < Hn);

    float bR = 0, bZ = 0, bN = 0;
    if (active) {
#pragma unroll
        for (int r = 0; r < 6; r++) {
            const int g = r >> 1, jj = r & 1;
            const float2* src = (const float2*)(Whh + ((size_t)g * Hn + j0 + jj) * Hn);
            unsigned* dst = sw + (warp * 6 + r) * 1024;
            for (int i = lane; i < 1024; i += 32) {
                __nv_bfloat162 b2 = __float22bfloat162_rn(__ldg(src + i));
                dst[i] = *(unsigned*)&b2;
            }
        }
        if (lane < 2) {
            bR = bhh[j0 + lane];
            bZ = bhh[Hn + j0 + lane];
            bN = bhh[2 * Hn + j0 + lane];
        }
    }
    __syncthreads();

    for (int t = 0; t < Tn; t++) {
        // per-lane gi for j0+lane (independent of h; issued early)
        float giR = 0, giZ = 0, giN = 0;
        if (active && lane < 2) {
            const float* gi = g_enc_gi + (size_t)t * G3n;
            giR = __ldcs(gi + j0 + lane);
            giZ = __ldcs(gi + Hn + j0 + lane);
            giN = __ldcs(gi + 2 * Hn + j0 + lane);
        }
        // cooperative h staging: 8 KB per block per step
        const float4* hg4 = (const float4*)g_h[t & 1];
#pragma unroll
        for (int i = tid; i < Hn / 4; i += ETHR) shh4[i] = __ldcg(hg4 + i);
        __syncthreads();

        if (active) {
            const uint4* w = sw4 + (size_t)warp * 6 * 256;
            float aR0 = 0, aR1 = 0, aZ0 = 0, aZ1 = 0, aN0 = 0, aN1 = 0;
#pragma unroll
            for (int c = 0; c < 8; c++) {
                const int idx = c * 32 + lane;
                float4 hA = shh4[2 * idx];
                float4 hB = shh4[2 * idx + 1];
                uint4 uR0 = w[idx];
                uint4 uR1 = w[256 + idx];
                uint4 uZ0 = w[512 + idx];
                uint4 uZ1 = w[768 + idx];
                uint4 uN0 = w[1024 + idx];
                uint4 uN1 = w[1280 + idx];
                ACC8(aR0, uR0, hA, hB)
                ACC8(aR1, uR1, hA, hB)
                ACC8(aZ0, uZ0, hA, hB)
                ACC8(aZ1, uZ1, hA, hB)
                ACC8(aN0, uN0, hA, hB)
                ACC8(aN1, uN1, hA, hB)
            }
#pragma unroll
            for (int off = 16; off > 0; off >>= 1) {
                aR0 += __shfl_xor_sync(0xffffffffu, aR0, off);
                aR1 += __shfl_xor_sync(0xffffffffu, aR1, off);
                aZ0 += __shfl_xor_sync(0xffffffffu, aZ0, off);
                aZ1 += __shfl_xor_sync(0xffffffffu, aZ1, off);
                aN0 += __shfl_xor_sync(0xffffffffu, aN0, off);
                aN1 += __shfl_xor_sync(0xffffffffu, aN1, off);
            }
            if (lane < 2) {
                const int j = j0 + lane;
                float aR = (lane == 0) ? aR0 : aR1;
                float aZ = (lane == 0) ? aZ0 : aZ1;
                float aN = (lane == 0) ? aN0 : aN1;
                float r = sigmoidf_acc(giR + aR + bR);
                float z = sigmoidf_acc(giZ + aZ + bZ);
                float n = tanhf(giN + r * (aN + bN));
                float hv = (1.0f - z) * n + z * shh[j];
                g_h[(t + 1) & 1][j] = hv;
                g_enc_out[(size_t)t * Hn + j] = hv;
                g_enc_outT[(size_t)j * Tn + t] = hv;
            }
        }
        gbar(g_arr_enc, g_rel_enc, (unsigned)(t + 1));
    }
}

// ---------------- persistent decoder: Whh in SMEM, 4 barriers/step -------------
// h is staged ONCE per step (phase A) into the shh region and reused in phase E.
#define DEC_WHH_BYTES (14 * 3 * Hn * 2)              // 172032
#define DEC_SMEM (DEC_WHH_BYTES + (DINn + Hn) * 4)   // 196608

__global__ void __launch_bounds__(DTHR, 1) dec_persistent(
    const float* __restrict__ dec_bih, const float* __restrict__ dec_bhh,
    const float* __restrict__ h2o_W, const float* __restrict__ h2o_b,
    const float* __restrict__ W_b,
    const float* __restrict__ attn_W, const float* __restrict__ attn_b,
    const float* __restrict__ o2h_W, const float* __restrict__ o2h_b,
    float* __restrict__ d_out)
{
    extern __shared__ char dsm[];
    __nv_bfloat16* swhh = (__nv_bfloat16*)dsm;
    float* sbuf = (float*)(dsm + DEC_WHH_BYTES);         // DINn floats
    float* shh  = sbuf + DINn;                            // Hn floats (h, per step)
    float4* shh4 = (float4*)shh;
    __shared__ float s_red[16];
    __shared__ float s_fval[16];
    __shared__ int   s_fidx[16];
    __shared__ float s_mx, s_lse;
    __shared__ int   s_am;

    const int warp = threadIdx.x >> 5;
    const int lane = threadIdx.x & 31;
    const int tid = threadIdx.x;
    const int bid = blockIdx.x;
    unsigned gen = 0;

    // preload this block's dec_Whh rows (once, reused 64 steps)
    if (warp < 14) {
        const int j = bid * 14 + warp;
        if (j < Hn) {
#pragma unroll
            for (int r = 0; r < 3; r++) {
                const uint4* src = (const uint4*)g_decWhh_bf + (size_t)(r * Hn + j) * (Hn / 8);
                uint4* dst = (uint4*)(swhh + ((size_t)warp * 3 + r) * Hn);
                for (int i = lane; i < Hn / 8; i += 32) dst[i] = __ldg(src + i);
            }
        }
    }
    __syncthreads();

    for (int s = 0; s < DSTEP; s++) {
        const float* hin = g_h[s & 1];

        // ---- Phase A: stage h (into shh, reused all step); Wd (warps 0..13);
        //               logits of h_s (warps 14..15, bid<64) ----
        {
            const float4* hg4 = (const float4*)hin;
#pragma unroll
            for (int i = tid; i < Hn / 4; i += DTHR) shh4[i] = __ldcg(hg4 + i);
            __syncthreads();
            if (warp < 14) {
                const int j = bid * 14 + warp;
                if (j < Hn) {
                    const uint4* row = (const uint4*)g_WW_bf + (size_t)j * (Hn / 8);
                    float acc = 0.f;
#pragma unroll
                    for (int c = 0; c < 8; c++) {
                        const int idx = c * 32 + lane;
                        float4 hA = shh4[2 * idx];
                        float4 hB = shh4[2 * idx + 1];
                        uint4 u = __ldg(row + idx);
                        ACC8(acc, u, hA, hB)
                    }
#pragma unroll
                    for (int off = 16; off > 0; off >>= 1)
                        acc += __shfl_down_sync(0xffffffffu, acc, off);
                    if (lane == 0) g_Wd[j] = acc + __ldg(W_b + j);
                }
            } else if (bid < 64) {
                const int o = bid * 2 + (warp - 14);   // 0..127
                const float4* row = (const float4*)(h2o_W + (size_t)o * Hn);
                float acc = 0.f;
#pragma unroll 4
                for (int c = 0; c < Hn / 128; c++) {
                    float4 w = __ldg(row + c * 32 + lane);
                    float4 hv = shh4[c * 32 + lane];
                    acc = fmaf(w.x, hv.x, acc); acc = fmaf(w.y, hv.y, acc);
                    acc = fmaf(w.z, hv.z, acc); acc = fmaf(w.w, hv.w, acc);
                }
#pragma unroll
                for (int off = 16; off > 0; off >>= 1)
                    acc += __shfl_down_sync(0xffffffffu, acc, off);
                if (lane == 0) g_logits[o] = acc + __ldg(h2o_b + o);
            }
        }
        gen++; gbar(g_arr_dec, g_rel_dec, gen);

        // ---- Phase B: scores (bid<128) | argmax + outs row s-1 (bid==128, s>0) ----
        if (bid < 128) {
            float4* swd = (float4*)sbuf;
            const float4* wd4 = (const float4*)g_Wd;
#pragma unroll
            for (int i = tid; i < Hn / 4; i += DTHR) swd[i] = __ldcg(wd4 + i);
            __syncthreads();
            if (warp < 4) {
                const int t = bid * 4 + warp;   // 0..511
                const float4* u4 = (const float4*)(g_U + (size_t)t * Hn);
                const float4* aw4 = (const float4*)attn_W;
                float acc = 0.f;
#pragma unroll 4
                for (int c = 0; c < Hn / 128; c++) {
                    float4 u = __ldg(u4 + c * 32 + lane);
                    float4 d = swd[c * 32 + lane];
                    float4 w = __ldg(aw4 + c * 32 + lane);
                    acc = fmaf(tanhf(u.x + d.x), w.x, acc);
                    acc = fmaf(tanhf(u.y + d.y), w.y, acc);
                    acc = fmaf(tanhf(u.z + d.z), w.z, acc);
                    acc = fmaf(tanhf(u.w + d.w), w.w, acc);
                }
#pragma unroll
                for (int off = 16; off > 0; off >>= 1)
                    acc += __shfl_down_sync(0xffffffffu, acc, off);
                if (lane == 0) g_scores[t] = acc + __ldg(attn_b);
            }
        } else if (bid == 128 && s > 0) {
            float lv = (tid < OUTn) ? __ldcg(g_logits + tid) : -INFINITY;
            float v = lv;
            int vi = tid;
#pragma unroll
            for (int off = 16; off > 0; off >>= 1) {
                float ov = __shfl_xor_sync(0xffffffffu, v, off);
                int oi = __shfl_xor_sync(0xffffffffu, vi, off);
                if (ov > v || (ov == v && oi < vi)) { v = ov; vi = oi; }
            }
            if (lane == 0) { s_fval[warp] = v; s_fidx[warp] = vi; }
            __syncthreads();
            if (tid == 0) {
                float mv = s_fval[0]; int mi = s_fidx[0];
#pragma unroll
                for (int w = 1; w < 16; w++)
                    if (s_fval[w] > mv || (s_fval[w] == mv && s_fidx[w] < mi)) {
                        mv = s_fval[w]; mi = s_fidx[w];
                    }
                s_mx = mv; s_am = mi;
            }
            __syncthreads();
            float mx = s_mx;
            float e = (tid < OUTn) ? expf(lv - mx) : 0.f;
            float sum = e;
#pragma unroll
            for (int off = 16; off > 0; off >>= 1)
                sum += __shfl_xor_sync(0xffffffffu, sum, off);
            if (lane == 0) s_fval[warp] = sum;
            __syncthreads();
            if (tid == 0) {
                float tot = 0.f;
#pragma unroll
                for (int w = 0; w < 16; w++) tot += s_fval[w];
                s_lse = logf(tot);
                g_idx = s_am;
            }
            __syncthreads();
            if (tid < OUTn)
                d_out[(size_t)(s - 1) * OUTn + tid] = lv - mx - s_lse;
        }
        gen++; gbar(g_arr_dec, g_rel_dec, gen);

        // ---- Phase C: softmax; ctx+din (bid<128, 16 jj each) | attns out (bid==128)
        if (bid <= 128) {
            float v = __ldcg(g_scores + tid);
            float m = v;
#pragma unroll
            for (int off = 16; off > 0; off >>= 1)
                m = fmaxf(m, __shfl_xor_sync(0xffffffffu, m, off));
            if (lane == 0) s_red[warp] = m;
            __syncthreads();
            float mx = s_red[0];
#pragma unroll
            for (int w = 1; w < 16; w++) mx = fmaxf(mx, s_red[w]);
            __syncthreads();
            float e = expf(v - mx);
            float sum = e;
#pragma unroll
            for (int off = 16; off > 0; off >>= 1)
                sum += __shfl_xor_sync(0xffffffffu, sum, off);
            if (lane == 0) s_red[warp] = sum;
            __syncthreads();
            float tot = 0.f;
#pragma unroll
            for (int w = 0; w < 16; w++) tot += s_red[w];
            float aw = e / tot;
            sbuf[tid] = aw;
            __syncthreads();
            if (bid == 128) {
                d_out[DSTEP * OUTn + (size_t)s * Tn + tid] = aw;
            } else {
                const int jj = bid * 16 + warp;   // 0..2047
                const float4* row = (const float4*)(g_enc_outT + (size_t)jj * Tn);
                const float4* aw4 = (const float4*)sbuf;
                float acc = 0.f;
#pragma unroll
                for (int c = 0; c < 4; c++) {
                    const int idx = c * 32 + lane;
                    float4 a = aw4[idx];
                    float4 eo = __ldg(row + idx);
                    acc = fmaf(a.x, eo.x, acc); acc = fmaf(a.y, eo.y, acc);
                    acc = fmaf(a.z, eo.z, acc); acc = fmaf(a.w, eo.w, acc);
                }
#pragma unroll
                for (int off = 16; off > 0; off >>= 1)
                    acc += __shfl_down_sync(0xffffffffu, acc, off);
                if (lane == 0) {
                    g_din[Hn + jj] = acc;
                    int idx;
                    asm volatile("ld.global.cg.s32 %0, [%1];" : "=r"(idx) : "l"(&g_idx));
                    float emb = __ldg(o2h_b + jj);
                    if (idx >= 0) emb += __ldg(o2h_W + (size_t)jj * OUTn + idx);
                    g_din[jj] = emb;
                }
            }
        }
        gen++; gbar(g_arr_dec, g_rel_dec, gen);

        // ---- Phase E: decoder GRU (warps 0..13; Whh from SMEM; h already in shh) --
        {
            float4* sdin4 = (float4*)sbuf;
            const float4* dg4 = (const float4*)g_din;
#pragma unroll
            for (int i = tid; i < DINn / 4; i += DTHR) sdin4[i] = __ldcg(dg4 + i);
            __syncthreads();

            const int j = bid * 14 + warp;
            if (warp < 14 && j < Hn) {
                const uint4* ir  = (const uint4*)g_decWih_bf + (size_t)j * (DINn / 8);
                const uint4* iz  = (const uint4*)g_decWih_bf + (size_t)(Hn + j) * (DINn / 8);
                const uint4* in_ = (const uint4*)g_decWih_bf + (size_t)(2 * Hn + j) * (DINn / 8);
                const uint4* hr  = (const uint4*)(swhh + ((size_t)warp * 3 + 0) * Hn);
                const uint4* hz  = (const uint4*)(swhh + ((size_t)warp * 3 + 1) * Hn);
                const uint4* hn  = (const uint4*)(swhh + ((size_t)warp * 3 + 2) * Hn);

                float a_r = 0.f, a_z = 0.f, a_in = 0.f, a_hn = 0.f;
#pragma unroll 4
                for (int c = 0; c < 16; c++) {
                    const int idx = c * 32 + lane;
                    float4 dA = sdin4[2 * idx];
                    float4 dB = sdin4[2 * idx + 1];
                    uint4 u0 = __ldg(ir + idx);
                    uint4 u1 = __ldg(iz + idx);
                    uint4 u2 = __ldg(in_ + idx);
                    ACC8(a_r, u0, dA, dB)
                    ACC8(a_z, u1, dA, dB)
                    ACC8(a_in, u2, dA, dB)
                }
#pragma unroll 4
                for (int c = 0; c < 8; c++) {
                    const int idx = c * 32 + lane;
                    float4 hA = shh4[2 * idx];
                    float4 hB = shh4[2 * idx + 1];
                    uint4 u0 = hr[idx];
                    uint4 u1 = hz[idx];
                    uint4 u2 = hn[idx];
                    ACC8(a_r, u0, hA, hB)
                    ACC8(a_z, u1, hA, hB)
                    ACC8(a_hn, u2, hA, hB)
                }
#pragma unroll
                for (int off = 16; off > 0; off >>= 1) {
                    a_r  += __shfl_down_sync(0xffffffffu, a_r,  off);
                    a_z  += __shfl_down_sync(0xffffffffu, a_z,  off);
                    a_in += __shfl_down_sync(0xffffffffu, a_in, off);
                    a_hn += __shfl_down_sync(0xffffffffu, a_hn, off);
                }
                if (lane == 0) {
                    float r = sigmoidf_acc(a_r + __ldg(dec_bih + j) + __ldg(dec_bhh + j));
                    float z = sigmoidf_acc(a_z + __ldg(dec_bih + Hn + j) + __ldg(dec_bhh + Hn + j));
                    float n = tanhf(a_in + __ldg(dec_bih + 2 * Hn + j)
                                    + r * (a_hn + __ldg(dec_bhh + 2 * Hn + j)));
                    g_h[(s + 1) & 1][j] = (1.0f - z) * n + z * shh[j];
                }
            }
        }
        gen++; gbar(g_arr_dec, g_rel_dec, gen);
    }

    // ---- tail: logits of h_DSTEP + final log_softmax (row DSTEP-1) ----
    if (bid < 8) {
        const int o = bid * 16 + warp;   // 0..127
        const float4* hg4 = (const float4*)g_h[DSTEP & 1];
        const float4* row = (const float4*)(h2o_W + (size_t)o * Hn);
        float acc = 0.f;
#pragma unroll 4
        for (int c = 0; c < Hn / 128; c++) {
            float4 w = __ldg(row + c * 32 + lane);
            float4 hv = __ldcg(hg4 + c * 32 + lane);
            acc = fmaf(w.x, hv.x, acc); acc = fmaf(w.y, hv.y, acc);
            acc = fmaf(w.z, hv.z, acc); acc = fmaf(w.w, hv.w, acc);
        }
#pragma unroll
        for (int off = 16; off > 0; off >>= 1)
            acc += __shfl_down_sync(0xffffffffu, acc, off);
        if (lane == 0) g_logits[o] = acc + __ldg(h2o_b + o);
    }
    gen++; gbar(g_arr_dec, g_rel_dec, gen);

    if (bid == 0) {
        float lv = (tid < OUTn) ? __ldcg(g_logits + tid) : -INFINITY;
        float v = lv;
#pragma unroll
        for (int off = 16; off > 0; off >>= 1)
            v = fmaxf(v, __shfl_xor_sync(0xffffffffu, v, off));
        if (lane == 0) s_fval[warp] = v;
        __syncthreads();
        if (tid == 0) {
            float mv = s_fval[0];
#pragma unroll
            for (int w = 1; w < 16; w++) mv = fmaxf(mv, s_fval[w]);
            s_mx = mv;
        }
        __syncthreads();
        float mx = s_mx;
        float e = (tid < OUTn) ? expf(lv - mx) : 0.f;
        float sum = e;
#pragma unroll
        for (int off = 16; off > 0; off >>= 1)
            sum += __shfl_xor_sync(0xffffffffu, sum, off);
        if (lane == 0) s_fval[warp] = sum;
        __syncthreads();
        if (tid == 0) {
            float tot = 0.f;
#pragma unroll
            for (int w = 0; w < 16; w++) tot += s_fval[w];
            s_lse = logf(tot);
        }
        __syncthreads();
        if (tid < OUTn)
            d_out[(size_t)(DSTEP - 1) * OUTn + tid] = lv - mx - s_lse;
    }
}

// ---------------- launch (R8 order: enc at captured slot 3) ----------------
extern "C" void kernel_launch(void* const* d_in, const int* in_sizes, int n_in,
                              void* d_out, int out_size)
{
    const float* x        = (const float*)d_in[0];
    const float* enc_Wih  = (const float*)d_in[1];
    const float* enc_Whh  = (const float*)d_in[2];
    const float* enc_bih  = (const float*)d_in[3];
    const float* enc_bhh  = (const float*)d_in[4];
    const float* dec_Wih  = (const float*)d_in[5];
    const float* dec_Whh  = (const float*)d_in[6];
    const float* dec_bih  = (const float*)d_in[7];
    const float* dec_bhh  = (const float*)d_in[8];
    const float* h2o_W    = (const float*)d_in[9];
    const float* h2o_b    = (const float*)d_in[10];
    const float* U_W      = (const float*)d_in[11];
    const float* U_b      = (const float*)d_in[12];
    const float* W_W      = (const float*)d_in[13];
    const float* W_b      = (const float*)d_in[14];
    const float* attn_W   = (const float*)d_in[15];
    const float* attn_b   = (const float*)d_in[16];
    const float* o2h_W    = (const float*)d_in[17];
    const float* o2h_b    = (const float*)d_in[18];
    float* out = (float*)d_out;
    (void)in_sizes; (void)n_in; (void)out_size;

    float *gi_ptr, *enc_out_ptr, *U_ptr;
    __nv_bfloat16 *wih_bf, *whh_bf, *ww_bf;
    cudaGetSymbolAddress((void**)&gi_ptr, g_enc_gi);
    cudaGetSymbolAddress((void**)&enc_out_ptr, g_enc_out);
    cudaGetSymbolAddress((void**)&U_ptr, g_U);
    cudaGetSymbolAddress((void**)&wih_bf, g_decWih_bf);
    cudaGetSymbolAddress((void**)&whh_bf, g_decWhh_bf);
    cudaGetSymbolAddress((void**)&ww_bf, g_WW_bf);

    cudaFuncSetAttribute(enc_persistent,
                         cudaFuncAttributeMaxDynamicSharedMemorySize, ENC_SMEM);
    cudaFuncSetAttribute(dec_persistent,
                         cudaFuncAttributeMaxDynamicSharedMemorySize, DEC_SMEM);

    // launch 0
    init_kernel<<<20, 256>>>();
    // launch 1: gi = x @ enc_Wih^T + bih
    gemm_nt_bias<<<dim3(G3n / 64, Tn / 64), 256>>>(x, enc_Wih, enc_bih, gi_ptr,
                                                   Tn, G3n, INn);
    // launch 2
    f2bf_kernel<<<1024, 256>>>(W_W, ww_bf, Hn * Hn / 2);
    // launch 3: encoder
    enc_persistent<<<NBLK, ETHR, ENC_SMEM>>>(enc_Whh, enc_bhh);
    // decoder prep
    f2bf_kernel<<<2048, 256>>>(dec_Wih, wih_bf, G3n * DINn / 2);
    f2bf_kernel<<<2048, 256>>>(dec_Whh, whh_bf, G3n * Hn / 2);
    gemm_nt_bias<<<dim3(Hn / 64, Tn / 64), 256>>>(enc_out_ptr, U_W, U_b, U_ptr,
                                                  Tn, Hn, Hn);
    // decoder
    dec_persistent<<<NBLK, DTHR, DEC_SMEM>>>(dec_bih, dec_bhh, h2o_W, h2o_b, W_b,
                                             attn_W, attn_b, o2h_W, o2h_b, out);
}